// round 1
// baseline (speedup 1.0000x reference)
#include <cuda_runtime.h>
#include <math.h>

#define NUM_G   1024
#define NPG     256
#define F       768      // in feats
#define H       128      // hidden = out feats
#define F4      (F/4)    // 192

#define A_NORM  (1.0f/sqrtf(518.0f))   // dinv_node * dinv_prompt = 1/sqrt(2*259)
#define P_SELF  (1.0f/259.0f)          // prompt self-loop dinv^2

// Scratch (device globals: no allocation allowed)
__device__ float d_S[NUM_G * F];       // per-graph feature sums [1024,768]
__device__ float d_vec1[H];            // (1/259)hp + A*(hc0+hc1) + b1
__device__ float d_cconst[2][2];       // per-class-j constant logit terms

// ---------------------------------------------------------------------------
// K0: graph-independent constants (1 block, 128 threads)
// hp = prompt @ W1 ; hc_j = class_j @ W1 ; class-node layer1+2 chain (constant
// across graphs) folded into d_cconst; prompt-side affine folded into d_vec1.
// ---------------------------------------------------------------------------
__global__ void k0_consts(const float* __restrict__ prompt,
                          const float* __restrict__ cls,
                          const float* __restrict__ W1,
                          const float* __restrict__ b1,
                          const float* __restrict__ W2,
                          const float* __restrict__ b2,
                          const float* __restrict__ Wfc,
                          const float* __restrict__ bfc) {
    int c = threadIdx.x;  // 0..127
    float hp = 0.f, hc0 = 0.f, hc1 = 0.f;
    for (int k = 0; k < F; ++k) {
        float w = W1[k * H + c];
        hp  = fmaf(prompt[k],      w, hp);
        hc0 = fmaf(cls[k],         w, hc0);
        hc1 = fmaf(cls[F + k],     w, hc1);
    }
    d_vec1[c] = P_SELF * hp + A_NORM * (hc0 + hc1) + b1[c];

    __shared__ float sh0[H], sh1[H];   // relu(layer1) at class nodes 0/1
    sh0[c] = fmaxf(A_NORM * hp + 0.5f * hc0 + b1[c], 0.f);
    sh1[c] = fmaxf(A_NORM * hp + 0.5f * hc1 + b1[c], 0.f);
    __syncthreads();

    float gc0 = 0.f, gc1 = 0.f;        // class relu(h1) @ W2
    for (int k = 0; k < H; ++k) {
        float w = W2[k * H + c];
        gc0 = fmaf(sh0[k], w, gc0);
        gc1 = fmaf(sh1[k], w, gc1);
    }
    __shared__ float s0[H], s1[H];
    s0[c] = 0.5f * gc0 + b2[c];        // self-loop weight 1/2 at class node
    s1[c] = 0.5f * gc1 + b2[c];
    __syncthreads();

    if (c < 4) {                       // const_j[k2] = s_j @ Wfc[:,k2] + bfc
        int j = c >> 1, k2 = c & 1;
        const float* s = j ? s1 : s0;
        float acc = bfc[k2];
        for (int i = 0; i < H; ++i) acc = fmaf(s[i], Wfc[i * 2 + k2], acc);
        d_cconst[j][k2] = acc;
    }
}

// ---------------------------------------------------------------------------
// K1: per-graph column sum of x. 1024 blocks x 192 threads, float4, streaming.
// This is the HBM-bound part: reads all 805 MB of x exactly once.
// ---------------------------------------------------------------------------
__global__ __launch_bounds__(F4) void k1_sum(const float* __restrict__ x) {
    const float4* x4 = reinterpret_cast<const float4*>(x);
    const float4* p = x4 + (size_t)blockIdx.x * (NPG * F4) + threadIdx.x;
    float4 acc = make_float4(0.f, 0.f, 0.f, 0.f);
#pragma unroll 8
    for (int r = 0; r < NPG; ++r) {
        float4 v = __ldcs(p + (size_t)r * F4);
        acc.x += v.x; acc.y += v.y; acc.z += v.z; acc.w += v.w;
    }
    reinterpret_cast<float4*>(d_S)[blockIdx.x * F4 + threadIdx.x] = acc;
}

// ---------------------------------------------------------------------------
// K2: per-graph chain. 128 blocks x 128 threads; each block owns 8 graphs.
//   hS = S@W1 (tiled, K-chunks of 64) -> relu(A*hS + vec1) -> @W2 -> @Wfc
//   -> logits -> log_softmax -> out rows (2g+j).
// ---------------------------------------------------------------------------
#define GB 8
__global__ __launch_bounds__(H) void k2_graphs(const float* __restrict__ W1,
                                               const float* __restrict__ W2,
                                               const float* __restrict__ Wfc,
                                               float* __restrict__ out) {
    __shared__ float sW[64 * H];       // W1 K-tile  (32 KB)
    __shared__ float sS[GB][64];       // S rows tile
    __shared__ float sH[GB][H];        // relu(layer1) at prompts
    __shared__ float sG[GB][H];        // layer2 pre-projection at prompts
    const int tid = threadIdx.x;       // output column
    const int g0 = blockIdx.x * GB;

    float acc[GB];
#pragma unroll
    for (int g = 0; g < GB; ++g) acc[g] = 0.f;

    for (int kb = 0; kb < F; kb += 64) {
        __syncthreads();
#pragma unroll
        for (int i = 0; i < 64; ++i)
            sW[i * H + tid] = W1[(kb + i) * H + tid];
        for (int i = tid; i < GB * 64; i += H) {
            int g = i >> 6, kk = i & 63;
            sS[g][kk] = d_S[(size_t)(g0 + g) * F + kb + kk];
        }
        __syncthreads();
#pragma unroll 4
        for (int kk = 0; kk < 64; ++kk) {
            float w = sW[kk * H + tid];
#pragma unroll
            for (int g = 0; g < GB; ++g)
                acc[g] = fmaf(sS[g][kk], w, acc[g]);
        }
    }

    // layer-1 at prompt nodes: relu(A*hS + vec1)
    const float v1 = d_vec1[tid];
#pragma unroll
    for (int g = 0; g < GB; ++g)
        sH[g][tid] = fmaxf(fmaf(A_NORM, acc[g], v1), 0.f);
    __syncthreads();

    // @ W2 (W2 stays L2-resident: 64 KB total)
    float acc2[GB];
#pragma unroll
    for (int g = 0; g < GB; ++g) acc2[g] = 0.f;
    for (int k = 0; k < H; ++k) {
        float w = W2[k * H + tid];
#pragma unroll
        for (int g = 0; g < GB; ++g)
            acc2[g] = fmaf(sH[g][k], w, acc2[g]);
    }
#pragma unroll
    for (int g = 0; g < GB; ++g) sG[g][tid] = acc2[g];
    __syncthreads();

    // final projection + log_softmax: 8 threads, one graph each
    if (tid < GB) {
        const int g = tid;
        float u0 = 0.f, u1 = 0.f;
        for (int c = 0; c < H; ++c) {
            float v = sG[g][c];
            u0 = fmaf(v, Wfc[2 * c],     u0);
            u1 = fmaf(v, Wfc[2 * c + 1], u1);
        }
#pragma unroll
        for (int j = 0; j < 2; ++j) {
            float z0 = fmaf(A_NORM, u0, d_cconst[j][0]);
            float z1 = fmaf(A_NORM, u1, d_cconst[j][1]);
            float m  = fmaxf(z0, z1);
            float lse = m + logf(expf(z0 - m) + expf(z1 - m));
            int row = (g0 + g) * 2 + j;
            out[row * 2 + 0] = z0 - lse;
            out[row * 2 + 1] = z1 - lse;
        }
    }
}

// ---------------------------------------------------------------------------
extern "C" void kernel_launch(void* const* d_in, const int* in_sizes, int n_in,
                              void* d_out, int out_size) {
    const float* x      = (const float*)d_in[0];
    const float* prompt = (const float*)d_in[1];
    const float* cls    = (const float*)d_in[2];
    const float* W1     = (const float*)d_in[3];
    const float* b1     = (const float*)d_in[4];
    const float* W2     = (const float*)d_in[5];
    const float* b2     = (const float*)d_in[6];
    const float* Wfc    = (const float*)d_in[7];
    const float* bfc    = (const float*)d_in[8];
    float* out = (float*)d_out;

    k0_consts<<<1, H>>>(prompt, cls, W1, b1, W2, b2, Wfc, bfc);
    k1_sum<<<NUM_G, F4>>>(x);
    k2_graphs<<<NUM_G / GB, H>>>(W1, W2, Wfc, out);
}

// round 4
// speedup vs baseline: 1.1702x; 1.1702x over previous
#include <cuda_runtime.h>
#include <math.h>

#define NUM_G   1024
#define NPG     256
#define F       768      // in feats
#define H       128      // hidden = out feats
#define F4      (F/4)    // 192

#define A_NORM  (1.0f/sqrtf(518.0f))   // dinv_node * dinv_prompt = 1/sqrt(2*259)
#define P_SELF  (1.0f/259.0f)          // prompt self-loop dinv^2

#define NSLICE  8        // k-parallel slices in k0

// Scratch (device globals: no allocation allowed)
__device__ float d_S[NUM_G * F];       // per-graph feature sums [1024,768]
__device__ float d_vec1[H];            // (1/259)hp + A*(hc0+hc1) + b1
__device__ float d_cconst[2][2];       // per-class-j constant logit terms

// ---------------------------------------------------------------------------
// K0: graph-independent constants. 1 block x 1024 threads:
// 8 k-slices x 128 output columns, shared-mem reduce. Was 108us at 128 thr
// (latency-serialized); now each dependent-load chain is 8x shorter and the
// SM has 32 warps to hide DRAM latency.
// ---------------------------------------------------------------------------
__global__ __launch_bounds__(NSLICE * H) void k0_consts(
                          const float* __restrict__ prompt,
                          const float* __restrict__ cls,
                          const float* __restrict__ W1,
                          const float* __restrict__ b1,
                          const float* __restrict__ W2,
                          const float* __restrict__ b2,
                          const float* __restrict__ Wfc,
                          const float* __restrict__ bfc) {
    __shared__ float pA[NSLICE][H], pB[NSLICE][H], pC[NSLICE][H];
    __shared__ float sh0[H], sh1[H], s0[H], s1[H];

    const int t = threadIdx.x;
    const int c = t & (H - 1);     // output column 0..127
    const int s = t >> 7;          // k-slice 0..7

    // ---- stage 1: hp/hc0/hc1 = {prompt,cls0,cls1} @ W1, k-split 8 ways ----
    {
        float hp = 0.f, hc0 = 0.f, hc1 = 0.f;
        const int k0 = s * (F / NSLICE);
#pragma unroll 4
        for (int k = k0; k < k0 + F / NSLICE; ++k) {
            float w = W1[k * H + c];
            hp  = fmaf(prompt[k],  w, hp);
            hc0 = fmaf(cls[k],     w, hc0);
            hc1 = fmaf(cls[F + k], w, hc1);
        }
        pA[s][c] = hp; pB[s][c] = hc0; pC[s][c] = hc1;
    }
    __syncthreads();
    if (s == 0) {
        float hp = 0.f, hc0 = 0.f, hc1 = 0.f;
#pragma unroll
        for (int i = 0; i < NSLICE; ++i) {
            hp += pA[i][c]; hc0 += pB[i][c]; hc1 += pC[i][c];
        }
        float b = b1[c];
        d_vec1[c] = P_SELF * hp + A_NORM * (hc0 + hc1) + b;
        sh0[c] = fmaxf(A_NORM * hp + 0.5f * hc0 + b, 0.f);
        sh1[c] = fmaxf(A_NORM * hp + 0.5f * hc1 + b, 0.f);
    }
    __syncthreads();

    // ---- stage 2: gc{0,1} = relu(h1_class) @ W2, k-split 8 ways ----
    {
        float g0 = 0.f, g1 = 0.f;
        const int k0 = s * (H / NSLICE);
#pragma unroll
        for (int k = k0; k < k0 + H / NSLICE; ++k) {
            float w = W2[k * H + c];
            g0 = fmaf(sh0[k], w, g0);
            g1 = fmaf(sh1[k], w, g1);
        }
        pA[s][c] = g0; pB[s][c] = g1;
    }
    __syncthreads();
    if (s == 0) {
        float g0 = 0.f, g1 = 0.f;
#pragma unroll
        for (int i = 0; i < NSLICE; ++i) { g0 += pA[i][c]; g1 += pB[i][c]; }
        float b = b2[c];
        s0[c] = 0.5f * g0 + b;          // class-node self-loop weight 1/2
        s1[c] = 0.5f * g1 + b;
    }
    __syncthreads();

    // ---- stage 3: const_j[k2] = s_j @ Wfc[:,k2] + bfc ; 4 warps, shfl ----
    if (t < 128) {
        int j  = t >> 6;               // warp pair -> class j (warps 0-1: j=0)
        int k2 = (t >> 5) & 1;         // warp parity -> logit column
        const float* sv = j ? s1 : s0;
        int lane = t & 31;
        float acc = 0.f;
#pragma unroll
        for (int i = lane; i < H; i += 32)
            acc = fmaf(sv[i], Wfc[i * 2 + k2], acc);
#pragma unroll
        for (int o = 16; o > 0; o >>= 1)
            acc += __shfl_down_sync(0xffffffffu, acc, o);
        if (lane == 0) d_cconst[j][k2] = acc + bfc[k2];
    }
}

// ---------------------------------------------------------------------------
// K1: per-graph column sum of x. 1024 blocks x 192 threads, float4, streaming.
// HBM-bound: reads all 805 MB of x exactly once (~85us at measured BW).
// ---------------------------------------------------------------------------
__global__ __launch_bounds__(F4) void k1_sum(const float* __restrict__ x) {
    const float4* x4 = reinterpret_cast<const float4*>(x);
    const float4* p = x4 + (size_t)blockIdx.x * (NPG * F4) + threadIdx.x;
    float4 acc = make_float4(0.f, 0.f, 0.f, 0.f);
#pragma unroll 8
    for (int r = 0; r < NPG; ++r) {
        float4 v = __ldcs(p + (size_t)r * F4);
        acc.x += v.x; acc.y += v.y; acc.z += v.z; acc.w += v.w;
    }
    reinterpret_cast<float4*>(d_S)[blockIdx.x * F4 + threadIdx.x] = acc;
}

// ---------------------------------------------------------------------------
// K2: per-graph chain. 128 blocks x 128 threads; each block owns 8 graphs.
//   hS = S@W1 (tiled, K-chunks of 64) -> relu(A*hS + vec1) -> @W2 -> @Wfc
//   -> logits -> log_softmax -> out rows (2g+j).
// ---------------------------------------------------------------------------
#define GB 8
__global__ __launch_bounds__(H) void k2_graphs(const float* __restrict__ W1,
                                               const float* __restrict__ W2,
                                               const float* __restrict__ Wfc,
                                               float* __restrict__ out) {
    __shared__ float sW[64 * H];       // W1 K-tile  (32 KB)
    __shared__ float sS[GB][64];       // S rows tile
    __shared__ float sH[GB][H];        // relu(layer1) at prompts
    __shared__ float sG[GB][H];        // layer2 pre-projection at prompts
    const int tid = threadIdx.x;       // output column
    const int g0 = blockIdx.x * GB;

    float acc[GB];
#pragma unroll
    for (int g = 0; g < GB; ++g) acc[g] = 0.f;

    for (int kb = 0; kb < F; kb += 64) {
        __syncthreads();
#pragma unroll
        for (int i = 0; i < 64; ++i)
            sW[i * H + tid] = W1[(kb + i) * H + tid];
        for (int i = tid; i < GB * 64; i += H) {
            int g = i >> 6, kk = i & 63;
            sS[g][kk] = d_S[(size_t)(g0 + g) * F + kb + kk];
        }
        __syncthreads();
#pragma unroll 4
        for (int kk = 0; kk < 64; ++kk) {
            float w = sW[kk * H + tid];
#pragma unroll
            for (int g = 0; g < GB; ++g)
                acc[g] = fmaf(sS[g][kk], w, acc[g]);
        }
    }

    // layer-1 at prompt nodes: relu(A*hS + vec1)
    const float v1 = d_vec1[tid];
#pragma unroll
    for (int g = 0; g < GB; ++g)
        sH[g][tid] = fmaxf(fmaf(A_NORM, acc[g], v1), 0.f);
    __syncthreads();

    // @ W2 (W2 stays L2-resident: 64 KB total)
    float acc2[GB];
#pragma unroll
    for (int g = 0; g < GB; ++g) acc2[g] = 0.f;
    for (int k = 0; k < H; ++k) {
        float w = W2[k * H + tid];
#pragma unroll
        for (int g = 0; g < GB; ++g)
            acc2[g] = fmaf(sH[g][k], w, acc2[g]);
    }
#pragma unroll
    for (int g = 0; g < GB; ++g) sG[g][tid] = acc2[g];
    __syncthreads();

    // final projection + log_softmax: 8 threads, one graph each
    if (tid < GB) {
        const int g = tid;
        float u0 = 0.f, u1 = 0.f;
        for (int c = 0; c < H; ++c) {
            float v = sG[g][c];
            u0 = fmaf(v, Wfc[2 * c],     u0);
            u1 = fmaf(v, Wfc[2 * c + 1], u1);
        }
#pragma unroll
        for (int j = 0; j < 2; ++j) {
            float z0 = fmaf(A_NORM, u0, d_cconst[j][0]);
            float z1 = fmaf(A_NORM, u1, d_cconst[j][1]);
            float m  = fmaxf(z0, z1);
            float lse = m + logf(expf(z0 - m) + expf(z1 - m));
            int row = (g0 + g) * 2 + j;
            out[row * 2 + 0] = z0 - lse;
            out[row * 2 + 1] = z1 - lse;
        }
    }
}

// ---------------------------------------------------------------------------
extern "C" void kernel_launch(void* const* d_in, const int* in_sizes, int n_in,
                              void* d_out, int out_size) {
    const float* x      = (const float*)d_in[0];
    const float* prompt = (const float*)d_in[1];
    const float* cls    = (const float*)d_in[2];
    const float* W1     = (const float*)d_in[3];
    const float* b1     = (const float*)d_in[4];
    const float* W2     = (const float*)d_in[5];
    const float* b2     = (const float*)d_in[6];
    const float* Wfc    = (const float*)d_in[7];
    const float* bfc    = (const float*)d_in[8];
    float* out = (float*)d_out;

    k0_consts<<<1, NSLICE * H>>>(prompt, cls, W1, b1, W2, b2, Wfc, bfc);
    k1_sum<<<NUM_G, F4>>>(x);
    k2_graphs<<<NUM_G / GB, H>>>(W1, W2, Wfc, out);
}